// round 8
// baseline (speedup 1.0000x reference)
#include <cuda_runtime.h>
#include <math.h>
#include <stdint.h>

// Problem constants
#define Bb   16
#define Ss   2048
#define KN   256
#define Dd   512
#define Mtot (Bb * Ss)
#define RSCALE 0.044194173824159216f

#define RSTR 20           // smem row stride in words (16 k + 4 pad)

// ---------------------------------------------------------------------------
// Scratch
// ---------------------------------------------------------------------------
__device__ float g_X[Mtot * Dd];
__device__ float g_Q[Mtot * Dd];
__device__ float g_K[Mtot * Dd];
__device__ float g_V[Mtot * Dd];
__device__ float g_S[67108864];           // 256 MB scores [B,S,S]
__device__ float2 g_MZ[Mtot];             // per-row (max, invZ)
__device__ float g_c[Mtot];
__device__ float g_sumO[Bb * Dd];
__device__ float g_cat[Bb * 2 * Dd];
__device__ float g_WT[3 * Dd * Dd];       // transposed Wq|Wk|Wv (one stream)
__device__ float g_WtT[Dd * KN];          // transposed W_t

// ---------------------------------------------------------------------------
// tf32 helpers
// ---------------------------------------------------------------------------
__device__ __forceinline__ uint32_t f2tf(float f) {
    uint32_t r;
    asm("cvt.rna.tf32.f32 %0, %1;" : "=r"(r) : "f"(f));
    return r;
}
__device__ __forceinline__ uint4 f2tf4(float4 v) {
    uint4 t; t.x = f2tf(v.x); t.y = f2tf(v.y); t.z = f2tf(v.z); t.w = f2tf(v.w);
    return t;
}

__device__ __forceinline__ void mma8(float c[4], const uint32_t a[4], const uint32_t b[2]) {
    asm volatile(
        "mma.sync.aligned.m16n8k8.row.col.f32.tf32.tf32.f32 "
        "{%0,%1,%2,%3}, {%4,%5,%6,%7}, {%8,%9}, {%0,%1,%2,%3};"
        : "+f"(c[0]), "+f"(c[1]), "+f"(c[2]), "+f"(c[3])
        : "r"(a[0]), "r"(a[1]), "r"(a[2]), "r"(a[3]), "r"(b[0]), "r"(b[1]));
}

// Warp computes a 64x64 subtile of the 128x128 CTA tile. Operands row-major:
// Arm[r*RSTR + k], Brm[n*RSTR + k], k-slab = 16 (2 k8 steps).
__device__ __forceinline__ void compute_slab(const uint32_t* __restrict__ Arm,
                                             const uint32_t* __restrict__ Brm,
                                             float acc[4][8][4],
                                             int lane, int wm, int wn)
{
    const int grp = lane >> 2;   // 0..7
    const int qd  = lane & 3;    // 0..3
    #pragma unroll
    for (int ks = 0; ks < 2; ks++) {
        const int k0 = ks * 8;
        uint32_t a[4][4], b[8][2];
        #pragma unroll
        for (int tm = 0; tm < 4; tm++) {
            const int m = wm * 64 + tm * 16 + grp;
            a[tm][0] = Arm[m * RSTR + k0 + qd];
            a[tm][1] = Arm[(m + 8) * RSTR + k0 + qd];
            a[tm][2] = Arm[m * RSTR + k0 + qd + 4];
            a[tm][3] = Arm[(m + 8) * RSTR + k0 + qd + 4];
        }
        #pragma unroll
        for (int tn = 0; tn < 8; tn++) {
            const int n = wn * 64 + tn * 8 + grp;
            b[tn][0] = Brm[n * RSTR + k0 + qd];
            b[tn][1] = Brm[n * RSTR + k0 + qd + 4];
        }
        #pragma unroll
        for (int tm = 0; tm < 4; tm++)
            #pragma unroll
            for (int tn = 0; tn < 8; tn++)
                mma8(acc[tm][tn], a[tm], b[tn]);
    }
}

// ---------------------------------------------------------------------------
// tf32 GEMM: C[M,512] = A[M,Kd] @ WT^T + bias (WT is [N][Kd] K-major).
// CTA 128x128, 128 threads (4 warps, 64x64 each), double-buffered smem.
// ---------------------------------------------------------------------------
__global__ __launch_bounds__(128, 2) void tf32_gemm_bias(const float* __restrict__ A,
                                                         const float* __restrict__ WT,
                                                         const float* __restrict__ bias,
                                                         float* __restrict__ C,
                                                         int Kd,
                                                         const int* __restrict__ lens)
{
    __shared__ uint32_t As[2][128 * RSTR];
    __shared__ uint32_t Bs[2][128 * RSTR];
    const int tid  = threadIdx.x;
    const int lane = tid & 31;
    const int w    = tid >> 5;
    const int wm   = w >> 1, wn = w & 1;
    const int row0 = blockIdx.x * 128;
    const int col0 = blockIdx.y * 128;

    if (lens) {
        const int L = lens[row0 / Ss] + 1;
        if ((row0 % Ss) >= L) return;
    }

    const int lr = tid >> 2;          // 0..31 (+32i)
    const int kq = (tid & 3) * 4;     // 0,4,8,12

    float4 aV[4], bV[4];
    #pragma unroll
    for (int i = 0; i < 4; i++) {
        aV[i] = *(const float4*)&A[(size_t)(row0 + lr + i * 32) * Kd + kq];
        bV[i] = *(const float4*)&WT[(size_t)(col0 + lr + i * 32) * Kd + kq];
    }
    #pragma unroll
    for (int i = 0; i < 4; i++) {
        *(uint4*)&As[0][(lr + i * 32) * RSTR + kq] = f2tf4(aV[i]);
        *(uint4*)&Bs[0][(lr + i * 32) * RSTR + kq] = f2tf4(bV[i]);
    }
    __syncthreads();

    float acc[4][8][4] = {};
    int buf = 0;
    for (int kt = 0; kt < Kd; kt += 16) {
        const bool more = (kt + 16 < Kd);
        if (more) {
            #pragma unroll
            for (int i = 0; i < 4; i++) {
                aV[i] = *(const float4*)&A[(size_t)(row0 + lr + i * 32) * Kd + kt + 16 + kq];
                bV[i] = *(const float4*)&WT[(size_t)(col0 + lr + i * 32) * Kd + kt + 16 + kq];
            }
        }
        compute_slab(As[buf], Bs[buf], acc, lane, wm, wn);
        if (more) {
            const int nb = buf ^ 1;
            #pragma unroll
            for (int i = 0; i < 4; i++) {
                *(uint4*)&As[nb][(lr + i * 32) * RSTR + kq] = f2tf4(aV[i]);
                *(uint4*)&Bs[nb][(lr + i * 32) * RSTR + kq] = f2tf4(bV[i]);
            }
            __syncthreads();
            buf = nb;
        }
    }

    const int grp = lane >> 2, qd = lane & 3;
    #pragma unroll
    for (int tm = 0; tm < 4; tm++) {
        #pragma unroll
        for (int tn = 0; tn < 8; tn++) {
            const int r = row0 + wm * 64 + tm * 16 + grp;
            const int c = col0 + wn * 64 + tn * 8 + qd * 2;
            const float b0 = bias[c], b1 = bias[c + 1];
            C[(size_t)r * Dd + c]           = acc[tm][tn][0] + b0;
            C[(size_t)r * Dd + c + 1]       = acc[tm][tn][1] + b1;
            C[(size_t)(r + 8) * Dd + c]     = acc[tm][tn][2] + b0;
            C[(size_t)(r + 8) * Dd + c + 1] = acc[tm][tn][3] + b1;
        }
    }
}

// ---------------------------------------------------------------------------
// Embed GEMM: X = (emb[data]*know) @ WtT^T + bt  (Kd = 256, WtT is [512][256])
// ---------------------------------------------------------------------------
__global__ __launch_bounds__(128, 2) void tf32_embed_gemm(const int* __restrict__ data,
                                                          const float* __restrict__ know,
                                                          const float* __restrict__ emb,
                                                          const float* __restrict__ WtT,
                                                          const float* __restrict__ bt,
                                                          float* __restrict__ C)
{
    __shared__ uint32_t As[2][128 * RSTR];
    __shared__ uint32_t Bs[2][128 * RSTR];
    __shared__ int sIdx[128];
    const int tid  = threadIdx.x;
    const int lane = tid & 31;
    const int w    = tid >> 5;
    const int wm   = w >> 1, wn = w & 1;
    const int row0 = blockIdx.x * 128;
    const int col0 = blockIdx.y * 128;

    sIdx[tid] = data[row0 + tid];
    __syncthreads();

    const int lr = tid >> 2;
    const int kq = (tid & 3) * 4;

    float4 aV[4], bV[4];
    #pragma unroll
    for (int i = 0; i < 4; i++) {
        float4 e = *(const float4*)&emb[(size_t)sIdx[lr + i * 32] * KN + kq];
        float4 k = *(const float4*)&know[(size_t)(row0 + lr + i * 32) * KN + kq];
        aV[i] = make_float4(e.x * k.x, e.y * k.y, e.z * k.z, e.w * k.w);
        bV[i] = *(const float4*)&WtT[(size_t)(col0 + lr + i * 32) * KN + kq];
    }
    #pragma unroll
    for (int i = 0; i < 4; i++) {
        *(uint4*)&As[0][(lr + i * 32) * RSTR + kq] = f2tf4(aV[i]);
        *(uint4*)&Bs[0][(lr + i * 32) * RSTR + kq] = f2tf4(bV[i]);
    }
    __syncthreads();

    float acc[4][8][4] = {};
    int buf = 0;
    for (int kt = 0; kt < KN; kt += 16) {
        const bool more = (kt + 16 < KN);
        if (more) {
            #pragma unroll
            for (int i = 0; i < 4; i++) {
                float4 e = *(const float4*)&emb[(size_t)sIdx[lr + i * 32] * KN + kt + 16 + kq];
                float4 k = *(const float4*)&know[(size_t)(row0 + lr + i * 32) * KN + kt + 16 + kq];
                aV[i] = make_float4(e.x * k.x, e.y * k.y, e.z * k.z, e.w * k.w);
                bV[i] = *(const float4*)&WtT[(size_t)(col0 + lr + i * 32) * KN + kt + 16 + kq];
            }
        }
        compute_slab(As[buf], Bs[buf], acc, lane, wm, wn);
        if (more) {
            const int nb = buf ^ 1;
            #pragma unroll
            for (int i = 0; i < 4; i++) {
                *(uint4*)&As[nb][(lr + i * 32) * RSTR + kq] = f2tf4(aV[i]);
                *(uint4*)&Bs[nb][(lr + i * 32) * RSTR + kq] = f2tf4(bV[i]);
            }
            __syncthreads();
            buf = nb;
        }
    }

    const int grp = lane >> 2, qd = lane & 3;
    #pragma unroll
    for (int tm = 0; tm < 4; tm++) {
        #pragma unroll
        for (int tn = 0; tn < 8; tn++) {
            const int r = row0 + wm * 64 + tm * 16 + grp;
            const int c = col0 + wn * 64 + tn * 8 + qd * 2;
            const float b0 = bt[c], b1 = bt[c + 1];
            C[(size_t)r * Dd + c]           = acc[tm][tn][0] + b0;
            C[(size_t)r * Dd + c + 1]       = acc[tm][tn][1] + b1;
            C[(size_t)(r + 8) * Dd + c]     = acc[tm][tn][2] + b0;
            C[(size_t)(r + 8) * Dd + c + 1] = acc[tm][tn][3] + b1;
        }
    }
}

// ---------------------------------------------------------------------------
// Scores (NT): S[b,q,k] = RSCALE * dot(Q[b,q,:], K[b,k,:]). Both operands
// naturally [row][D] -> row-major loaders. Masked k-tiles skipped.
// ---------------------------------------------------------------------------
__global__ __launch_bounds__(128, 2) void tf32_scores(const float* __restrict__ Q,
                                                      const float* __restrict__ Km,
                                                      float* __restrict__ Sout,
                                                      const int* __restrict__ lens)
{
    const int b   = blockIdx.z;
    const int q0  = blockIdx.x * 128;
    const int k0c = blockIdx.y * 128;
    const int L   = lens[b] + 1;
    if (k0c >= L) return;

    __shared__ uint32_t As[2][128 * RSTR];
    __shared__ uint32_t Bs[2][128 * RSTR];
    const int tid  = threadIdx.x;
    const int lane = tid & 31;
    const int w    = tid >> 5;
    const int wm   = w >> 1, wn = w & 1;

    const float* Qb = Q  + (size_t)b * Ss * Dd;
    const float* Kb = Km + (size_t)b * Ss * Dd;

    const int lr = tid >> 2;
    const int kq = (tid & 3) * 4;

    float4 aV[4], bV[4];
    #pragma unroll
    for (int i = 0; i < 4; i++) {
        aV[i] = *(const float4*)&Qb[(size_t)(q0 + lr + i * 32) * Dd + kq];
        bV[i] = *(const float4*)&Kb[(size_t)(k0c + lr + i * 32) * Dd + kq];
    }
    #pragma unroll
    for (int i = 0; i < 4; i++) {
        *(uint4*)&As[0][(lr + i * 32) * RSTR + kq] = f2tf4(aV[i]);
        *(uint4*)&Bs[0][(lr + i * 32) * RSTR + kq] = f2tf4(bV[i]);
    }
    __syncthreads();

    float acc[4][8][4] = {};
    int buf = 0;
    for (int kt = 0; kt < Dd; kt += 16) {
        const bool more = (kt + 16 < Dd);
        if (more) {
            #pragma unroll
            for (int i = 0; i < 4; i++) {
                aV[i] = *(const float4*)&Qb[(size_t)(q0 + lr + i * 32) * Dd + kt + 16 + kq];
                bV[i] = *(const float4*)&Kb[(size_t)(k0c + lr + i * 32) * Dd + kt + 16 + kq];
            }
        }
        compute_slab(As[buf], Bs[buf], acc, lane, wm, wn);
        if (more) {
            const int nb = buf ^ 1;
            #pragma unroll
            for (int i = 0; i < 4; i++) {
                *(uint4*)&As[nb][(lr + i * 32) * RSTR + kq] = f2tf4(aV[i]);
                *(uint4*)&Bs[nb][(lr + i * 32) * RSTR + kq] = f2tf4(bV[i]);
            }
            __syncthreads();
            buf = nb;
        }
    }

    float* Sb = Sout + (size_t)b * Ss * Ss;
    const int grp = lane >> 2, qd = lane & 3;
    #pragma unroll
    for (int tm = 0; tm < 4; tm++) {
        #pragma unroll
        for (int tn = 0; tn < 8; tn++) {
            const int q = q0 + wm * 64 + tm * 16 + grp;
            const int k = k0c + wn * 64 + tn * 8 + qd * 2;
            Sb[(size_t)q * Ss + k]           = acc[tm][tn][0] * RSCALE;
            Sb[(size_t)q * Ss + k + 1]       = acc[tm][tn][1] * RSCALE;
            Sb[(size_t)(q + 8) * Ss + k]     = acc[tm][tn][2] * RSCALE;
            Sb[(size_t)(q + 8) * Ss + k + 1] = acc[tm][tn][3] * RSCALE;
        }
    }
}

// ---------------------------------------------------------------------------
// Weight transpose: W[Kd][Nd] -> WT[Nd][Kd]
// ---------------------------------------------------------------------------
__global__ void transpose_kernel(const float* __restrict__ W, float* __restrict__ WT,
                                 int Kd, int Nd)
{
    __shared__ float t[32][33];
    const int k0 = blockIdx.x * 32, n0 = blockIdx.y * 32;
    const int tx = threadIdx.x, ty = threadIdx.y;   // 32x8
    #pragma unroll
    for (int i = 0; i < 32; i += 8)
        t[ty + i][tx] = W[(size_t)(k0 + ty + i) * Nd + n0 + tx];
    __syncthreads();
    #pragma unroll
    for (int i = 0; i < 32; i += 8)
        WT[(size_t)(n0 + ty + i) * Kd + k0 + tx] = t[tx][ty + i];
}

// ---------------------------------------------------------------------------
// Row stats: per (b,q) row: store (max, 1/sum(exp(s-max))) -- no p write-back.
// ---------------------------------------------------------------------------
__global__ void rowstats_kernel(const float* __restrict__ Sm,
                                float2* __restrict__ MZ,
                                const int* __restrict__ lens)
{
    __shared__ float red[256];
    const int r   = blockIdx.x;
    const int b   = r / Ss;
    const int L   = lens[b] + 1;
    const int tid = threadIdx.x;
    const float* row = Sm + (size_t)r * Ss;

    float mx = -1e30f;
    for (int k = tid; k < L; k += 256) mx = fmaxf(mx, row[k]);
    red[tid] = mx;
    __syncthreads();
    for (int s = 128; s > 0; s >>= 1) {
        if (tid < s) red[tid] = fmaxf(red[tid], red[tid + s]);
        __syncthreads();
    }
    mx = red[0];
    __syncthreads();

    float z = 0.f;
    for (int k = tid; k < L; k += 256) z += __expf(row[k] - mx);
    red[tid] = z;
    __syncthreads();
    for (int s = 128; s > 0; s >>= 1) {
        if (tid < s) red[tid] += red[tid + s];
        __syncthreads();
    }
    if (tid == 0) MZ[r] = make_float2(mx, 1.0f / red[0]);
}

// ---------------------------------------------------------------------------
// Column sums: c[b,k] = sum_q exp(s[b,q,k]-m_q) * invZ_q
// ---------------------------------------------------------------------------
__global__ void colsum_kernel(const float* __restrict__ Sm,
                              const float2* __restrict__ MZ,
                              float* __restrict__ c,
                              const int* __restrict__ lens)
{
    const int b = blockIdx.y;
    const int k = blockIdx.x * 256 + threadIdx.x;
    const int L = lens[b] + 1;
    if (k >= L) { c[b * Ss + k] = 0.0f; return; }

    const float* sp = Sm + (size_t)b * Ss * Ss + k;
    const float2* mz = MZ + b * Ss;
    float acc = 0.f;
    #pragma unroll 1
    for (int q = 0; q < Ss; q += 4) {
        float s0 = sp[(size_t)(q + 0) * Ss];
        float s1 = sp[(size_t)(q + 1) * Ss];
        float s2 = sp[(size_t)(q + 2) * Ss];
        float s3 = sp[(size_t)(q + 3) * Ss];
        float2 m0 = mz[q + 0], m1 = mz[q + 1], m2 = mz[q + 2], m3 = mz[q + 3];
        acc += __expf(s0 - m0.x) * m0.y + __expf(s1 - m1.x) * m1.y
             + __expf(s2 - m2.x) * m2.y + __expf(s3 - m3.x) * m3.y;
    }
    c[b * Ss + k] = acc;
}

// ---------------------------------------------------------------------------
// sumO[b,d] = sum_{k<L} c[b,k] * V[b,k,d]
// ---------------------------------------------------------------------------
__global__ void sumo_kernel(const float* __restrict__ c,
                            const float* __restrict__ V,
                            float* __restrict__ sumO,
                            const int* __restrict__ lens)
{
    const int b = blockIdx.y;
    const int d = blockIdx.x * 128 + threadIdx.x;
    const int L = lens[b] + 1;
    const float* Vb = V + (size_t)b * Ss * Dd;
    const float* cb = c + b * Ss;
    float acc = 0.f;
    #pragma unroll 4
    for (int k = 0; k < L; k++)
        acc += cb[k] * Vb[(size_t)k * Dd + d];
    sumO[b * Dd + d] = acc;
}

// ---------------------------------------------------------------------------
// sa[b,n] = sumO[b,:] @ Wo[:,n] + S * bo[n]   -> g_cat[b, st*D + n]
// ---------------------------------------------------------------------------
__global__ void sa_kernel(const float* __restrict__ sumO,
                          const float* __restrict__ Wo,
                          const float* __restrict__ bo,
                          float* __restrict__ cat,
                          int st)
{
    __shared__ float sO[Dd];
    const int b = blockIdx.y;
    const int n = blockIdx.x * 256 + threadIdx.x;
    for (int i = threadIdx.x; i < Dd; i += 256) sO[i] = sumO[b * Dd + i];
    __syncthreads();
    float acc = (float)Ss * bo[n];
    #pragma unroll 8
    for (int d = 0; d < Dd; d++)
        acc += sO[d] * Wo[(size_t)d * Dd + n];
    cat[b * (2 * Dd) + st * Dd + n] = acc;
}

// ---------------------------------------------------------------------------
// out[b,j] = tanh(cat[b,:] @ W_out[:,j] + b_out[j])
// ---------------------------------------------------------------------------
__global__ void final_kernel(const float* __restrict__ cat,
                             const float* __restrict__ Wout,
                             const float* __restrict__ bout,
                             float* __restrict__ out)
{
    __shared__ float sc[2 * Dd];
    const int b = blockIdx.x;
    const int j = threadIdx.x;
    for (int i = threadIdx.x; i < 2 * Dd; i += 256) sc[i] = cat[b * (2 * Dd) + i];
    __syncthreads();
    float acc = bout[j];
    #pragma unroll 8
    for (int i = 0; i < 2 * Dd; i++)
        acc += sc[i] * Wout[(size_t)i * KN + j];
    out[b * KN + j] = tanhf(acc);
}

// ---------------------------------------------------------------------------
// Launch
// ---------------------------------------------------------------------------
extern "C" void kernel_launch(void* const* d_in, const int* in_sizes, int n_in,
                              void* d_out, int out_size)
{
    const int*   data0 = (const int*)  d_in[0];
    const float* know0 = (const float*)d_in[1];
    const int*   len0  = (const int*)  d_in[2];
    const int*   data1 = (const int*)  d_in[3];
    const float* know1 = (const float*)d_in[4];
    const int*   len1  = (const int*)  d_in[5];
    const float* emb   = (const float*)d_in[6];
    const float* Wt    = (const float*)d_in[7];
    const float* bt    = (const float*)d_in[8];
    const float* Wq[2] = {(const float*)d_in[9],  (const float*)d_in[17]};
    const float* bq[2] = {(const float*)d_in[10], (const float*)d_in[18]};
    const float* Wk[2] = {(const float*)d_in[11], (const float*)d_in[19]};
    const float* bk[2] = {(const float*)d_in[12], (const float*)d_in[20]};
    const float* Wv[2] = {(const float*)d_in[13], (const float*)d_in[21]};
    const float* bv[2] = {(const float*)d_in[14], (const float*)d_in[22]};
    const float* Wo[2] = {(const float*)d_in[15], (const float*)d_in[23]};
    const float* bo[2] = {(const float*)d_in[16], (const float*)d_in[24]};
    const float* Wout  = (const float*)d_in[25];
    const float* bout  = (const float*)d_in[26];
    float* out = (float*)d_out;

    const int*   datas[2] = {data0, data1};
    const float* knows[2] = {know0, know1};
    const int*   lens [2] = {len0, len1};

    float *pX, *pQ, *pK, *pV, *pS, *pC, *pSO, *pCat, *pWT, *pWtT;
    float2* pMZ;
    cudaGetSymbolAddress((void**)&pX,   g_X);
    cudaGetSymbolAddress((void**)&pQ,   g_Q);
    cudaGetSymbolAddress((void**)&pK,   g_K);
    cudaGetSymbolAddress((void**)&pV,   g_V);
    cudaGetSymbolAddress((void**)&pS,   g_S);
    cudaGetSymbolAddress((void**)&pMZ,  g_MZ);
    cudaGetSymbolAddress((void**)&pC,   g_c);
    cudaGetSymbolAddress((void**)&pSO,  g_sumO);
    cudaGetSymbolAddress((void**)&pCat, g_cat);
    cudaGetSymbolAddress((void**)&pWT,  g_WT);
    cudaGetSymbolAddress((void**)&pWtT, g_WtT);

    const dim3 tB(32, 8);
    const dim3 gGemm(Mtot / 128, Dd / 128);     // 256 x 4
    const dim3 gScore(Ss / 128, Ss / 128, Bb);  // 16 x 16 x 16

    // W_t transpose (once): [256][512] -> [512][256]
    transpose_kernel<<<dim3(KN / 32, Dd / 32), tB>>>(Wt, pWtT, KN, Dd);

    for (int st = 0; st < 2; st++) {
        transpose_kernel<<<dim3(Dd / 32, Dd / 32), tB>>>(Wq[st], pWT,               Dd, Dd);
        transpose_kernel<<<dim3(Dd / 32, Dd / 32), tB>>>(Wk[st], pWT + Dd * Dd,     Dd, Dd);
        transpose_kernel<<<dim3(Dd / 32, Dd / 32), tB>>>(Wv[st], pWT + 2 * Dd * Dd, Dd, Dd);

        tf32_embed_gemm<<<gGemm, 128>>>(datas[st], knows[st], emb, pWtT, bt, pX);
        tf32_gemm_bias<<<gGemm, 128>>>(pX, pWT,               bq[st], pQ, Dd, nullptr);
        tf32_gemm_bias<<<gGemm, 128>>>(pX, pWT + Dd * Dd,     bk[st], pK, Dd, lens[st]);
        tf32_gemm_bias<<<gGemm, 128>>>(pX, pWT + 2 * Dd * Dd, bv[st], pV, Dd, lens[st]);
        tf32_scores<<<gScore, 128>>>(pQ, pK, pS, lens[st]);
        rowstats_kernel<<<Mtot, 256>>>(pS, pMZ, lens[st]);
        colsum_kernel<<<dim3(Ss / 256, Bb), 256>>>(pS, pMZ, pC, lens[st]);
        sumo_kernel<<<dim3(Dd / 128, Bb), 128>>>(pC, pV, pSO, lens[st]);
        sa_kernel<<<dim3(Dd / 256, Bb), 256>>>(pSO, Wo[st], bo[st], pCat, st);
    }
    final_kernel<<<Bb, 256>>>(pCat, Wout, bout, out);
}

// round 11
// speedup vs baseline: 1.6602x; 1.6602x over previous
#include <cuda_runtime.h>
#include <math.h>
#include <stdint.h>

// Problem constants
#define Bb   16
#define Ss   2048
#define KN   256
#define Dd   512
#define Mtot (Bb * Ss)
#define RSCALE 0.044194173824159216f

#define STR 136   // smem row stride (words)

// ---------------------------------------------------------------------------
// Scratch (per-stream where needed)
// ---------------------------------------------------------------------------
__device__ float g_X[2][Mtot * Dd];
__device__ float g_Q[2][Mtot * Dd];
__device__ float g_K[2][Mtot * Dd];
__device__ float g_V[2][Mtot * Dd];
__device__ float g_S[2][67108864];          // 2 x 256 MB scores [B,S,S]
__device__ float2 g_MZ[2 * Mtot];           // per-row (max, invZ)
__device__ float g_c[2 * Mtot];
__device__ float g_sumO[2 * Bb * Dd];
__device__ float g_cat[Bb * 2 * Dd];

// ---------------------------------------------------------------------------
// tf32 helpers (R6-proven core)
// ---------------------------------------------------------------------------
__device__ __forceinline__ uint32_t f2tf(float f) {
    uint32_t r;
    asm("cvt.rna.tf32.f32 %0, %1;" : "=r"(r) : "f"(f));
    return r;
}

__device__ __forceinline__ void mma8(float c[4], const uint32_t a[4], const uint32_t b[2]) {
    asm volatile(
        "mma.sync.aligned.m16n8k8.row.col.f32.tf32.tf32.f32 "
        "{%0,%1,%2,%3}, {%4,%5,%6,%7}, {%8,%9}, {%0,%1,%2,%3};"
        : "+f"(c[0]), "+f"(c[1]), "+f"(c[2]), "+f"(c[3])
        : "r"(a[0]), "r"(a[1]), "r"(a[2]), "r"(a[3]), "r"(b[0]), "r"(b[1]));
}

// Warp computes a 64(M) x 32(N) subtile of the 128x128 CTA tile.
__device__ __forceinline__ void compute_slab(const uint32_t As[16][STR],
                                             const uint32_t Bs[16][STR],
                                             float acc[4][4][4],
                                             int lane, int wm, int wn)
{
    const int grp = lane >> 2;
    const int qd  = lane & 3;
    const int mb0 = wm * 64;
    const int nb0 = wn * 32;
    #pragma unroll
    for (int ks = 0; ks < 2; ks++) {
        const int k0 = ks * 8;
        uint32_t a[4][4], b[4][2];
        #pragma unroll
        for (int tm = 0; tm < 4; tm++) {
            const int m = mb0 + tm * 16 + grp;
            a[tm][0] = As[k0 + qd][m];
            a[tm][1] = As[k0 + qd][m + 8];
            a[tm][2] = As[k0 + qd + 4][m];
            a[tm][3] = As[k0 + qd + 4][m + 8];
        }
        #pragma unroll
        for (int tn = 0; tn < 4; tn++) {
            const int n = nb0 + tn * 8 + grp;
            b[tn][0] = Bs[k0 + qd][n];
            b[tn][1] = Bs[k0 + qd + 4][n];
        }
        #pragma unroll
        for (int tm = 0; tm < 4; tm++)
            #pragma unroll
            for (int tn = 0; tn < 4; tn++)
                mma8(acc[tm][tn], a[tm], b[tn]);
    }
}

// ---------------------------------------------------------------------------
// Args for the merged Q/K/V GEMM launch
// ---------------------------------------------------------------------------
struct QKVArgs {
    const float* W[6];      // Wq0,Wk0,Wv0,Wq1,Wk1,Wv1   ([K][N] row-major)
    const float* bias[6];
    float*       C[6];      // Q0,K0,V0,Q1,K1,V1
    const float* A[2];      // X0, X1
    const int*   lens[2];
};

// ---------------------------------------------------------------------------
// Merged Q/K/V GEMM: z = st*3 + op.  C = A @ W + bias.  K,V skip masked rows.
// CTA 128x128, BK=16, 256 threads, double-buffered (R6 core).
// ---------------------------------------------------------------------------
__global__ __launch_bounds__(256) void tf32_qkv(QKVArgs args)
{
    __shared__ uint32_t As[2][16][STR];
    __shared__ uint32_t Bs[2][16][STR];
    const int z    = blockIdx.z;
    const int st   = (z >= 3) ? 1 : 0;
    const int op   = z - st * 3;
    const int tid  = threadIdx.x;
    const int lane = tid & 31;
    const int w    = tid >> 5;
    const int wm   = w >> 2, wn = w & 3;
    const int row0 = blockIdx.x * 128;
    const int col0 = blockIdx.y * 128;

    if (op != 0) {   // K, V: masked row-tiles
        const int L = args.lens[st][row0 / Ss] + 1;
        if ((row0 % Ss) >= L) return;
    }

    const float* A    = args.A[st];
    const float* W    = args.W[z];
    const float* bias = args.bias[z];
    float*       C    = args.C[z];

    const int ar  = tid >> 2;
    const int akq = (tid & 3) * 4;
    const int bk  = tid >> 4;
    const int bn  = (tid & 15) * 8;

    const float* pa0 = &A[(size_t)(row0 + ar) * Dd + akq];
    const float* pa1 = &A[(size_t)(row0 + ar + 64) * Dd + akq];
    const float* pw  = &W[(size_t)bk * Dd + col0 + bn];

    float4 ra0 = *(const float4*)pa0;
    float4 ra1 = *(const float4*)pa1;
    float4 rb0 = *(const float4*)pw;
    float4 rb1 = *(const float4*)(pw + 4);

    As[0][akq + 0][ar] = f2tf(ra0.x); As[0][akq + 1][ar] = f2tf(ra0.y);
    As[0][akq + 2][ar] = f2tf(ra0.z); As[0][akq + 3][ar] = f2tf(ra0.w);
    As[0][akq + 0][ar + 64] = f2tf(ra1.x); As[0][akq + 1][ar + 64] = f2tf(ra1.y);
    As[0][akq + 2][ar + 64] = f2tf(ra1.z); As[0][akq + 3][ar + 64] = f2tf(ra1.w);
    {
        uint4 v0 = {f2tf(rb0.x), f2tf(rb0.y), f2tf(rb0.z), f2tf(rb0.w)};
        uint4 v1 = {f2tf(rb1.x), f2tf(rb1.y), f2tf(rb1.z), f2tf(rb1.w)};
        *(uint4*)&Bs[0][bk][bn]     = v0;
        *(uint4*)&Bs[0][bk][bn + 4] = v1;
    }
    __syncthreads();

    float acc[4][4][4] = {};
    int buf = 0;
    for (int kt = 0; kt < Dd; kt += 16) {
        const bool more = (kt + 16 < Dd);
        if (more) {
            ra0 = *(const float4*)(pa0 + kt + 16);
            ra1 = *(const float4*)(pa1 + kt + 16);
            rb0 = *(const float4*)(pw + (size_t)(kt + 16) * Dd);
            rb1 = *(const float4*)(pw + (size_t)(kt + 16) * Dd + 4);
        }
        compute_slab(As[buf], Bs[buf], acc, lane, wm, wn);
        if (more) {
            const int nb = buf ^ 1;
            As[nb][akq + 0][ar] = f2tf(ra0.x); As[nb][akq + 1][ar] = f2tf(ra0.y);
            As[nb][akq + 2][ar] = f2tf(ra0.z); As[nb][akq + 3][ar] = f2tf(ra0.w);
            As[nb][akq + 0][ar + 64] = f2tf(ra1.x); As[nb][akq + 1][ar + 64] = f2tf(ra1.y);
            As[nb][akq + 2][ar + 64] = f2tf(ra1.z); As[nb][akq + 3][ar + 64] = f2tf(ra1.w);
            uint4 v0 = {f2tf(rb0.x), f2tf(rb0.y), f2tf(rb0.z), f2tf(rb0.w)};
            uint4 v1 = {f2tf(rb1.x), f2tf(rb1.y), f2tf(rb1.z), f2tf(rb1.w)};
            *(uint4*)&Bs[nb][bk][bn]     = v0;
            *(uint4*)&Bs[nb][bk][bn + 4] = v1;
            __syncthreads();
            buf = nb;
        }
    }

    const int grp = lane >> 2, qd = lane & 3;
    #pragma unroll
    for (int tm = 0; tm < 4; tm++) {
        #pragma unroll
        for (int tn = 0; tn < 4; tn++) {
            const int r = row0 + wm * 64 + tm * 16 + grp;
            const int c = col0 + wn * 32 + tn * 8 + qd * 2;
            const float b0 = bias[c], b1 = bias[c + 1];
            C[(size_t)r * Dd + c]           = acc[tm][tn][0] + b0;
            C[(size_t)r * Dd + c + 1]       = acc[tm][tn][1] + b1;
            C[(size_t)(r + 8) * Dd + c]     = acc[tm][tn][2] + b0;
            C[(size_t)(r + 8) * Dd + c + 1] = acc[tm][tn][3] + b1;
        }
    }
}

// ---------------------------------------------------------------------------
// Merged embed GEMM (z = stream): X[st] = (emb[data]*know) @ W_t + b_t
// ---------------------------------------------------------------------------
__global__ __launch_bounds__(256) void tf32_embed(const int* __restrict__ d0,
                                                  const float* __restrict__ kn0,
                                                  const int* __restrict__ d1,
                                                  const float* __restrict__ kn1,
                                                  const float* __restrict__ emb,
                                                  const float* __restrict__ Wt,
                                                  const float* __restrict__ bt,
                                                  float* __restrict__ X0,
                                                  float* __restrict__ X1)
{
    __shared__ uint32_t As[2][16][STR];
    __shared__ uint32_t Bs[2][16][STR];
    __shared__ int sIdx[128];
    const int st   = blockIdx.z;
    const int* data = st ? d1 : d0;
    const float* know = st ? kn1 : kn0;
    float* C = st ? X1 : X0;

    const int tid  = threadIdx.x;
    const int lane = tid & 31;
    const int w    = tid >> 5;
    const int wm   = w >> 2, wn = w & 3;
    const int row0 = blockIdx.x * 128;
    const int col0 = blockIdx.y * 128;

    if (tid < 128) sIdx[tid] = data[row0 + tid];
    __syncthreads();

    const int ar  = tid >> 2;
    const int akq = (tid & 3) * 4;
    const int bk  = tid >> 4;
    const int bn  = (tid & 15) * 8;

    const float* pe0 = &emb[(size_t)sIdx[ar] * KN + akq];
    const float* pe1 = &emb[(size_t)sIdx[ar + 64] * KN + akq];
    const float* pk0 = &know[(size_t)(row0 + ar) * KN + akq];
    const float* pk1 = &know[(size_t)(row0 + ar + 64) * KN + akq];
    const float* pw  = &Wt[(size_t)bk * Dd + col0 + bn];

    float4 ea0 = *(const float4*)pe0;
    float4 ka0 = *(const float4*)pk0;
    float4 ea1 = *(const float4*)pe1;
    float4 ka1 = *(const float4*)pk1;
    float4 rb0 = *(const float4*)pw;
    float4 rb1 = *(const float4*)(pw + 4);

    As[0][akq + 0][ar] = f2tf(ea0.x * ka0.x); As[0][akq + 1][ar] = f2tf(ea0.y * ka0.y);
    As[0][akq + 2][ar] = f2tf(ea0.z * ka0.z); As[0][akq + 3][ar] = f2tf(ea0.w * ka0.w);
    As[0][akq + 0][ar + 64] = f2tf(ea1.x * ka1.x); As[0][akq + 1][ar + 64] = f2tf(ea1.y * ka1.y);
    As[0][akq + 2][ar + 64] = f2tf(ea1.z * ka1.z); As[0][akq + 3][ar + 64] = f2tf(ea1.w * ka1.w);
    {
        uint4 v0 = {f2tf(rb0.x), f2tf(rb0.y), f2tf(rb0.z), f2tf(rb0.w)};
        uint4 v1 = {f2tf(rb1.x), f2tf(rb1.y), f2tf(rb1.z), f2tf(rb1.w)};
        *(uint4*)&Bs[0][bk][bn]     = v0;
        *(uint4*)&Bs[0][bk][bn + 4] = v1;
    }
    __syncthreads();

    float acc[4][4][4] = {};
    int buf = 0;
    for (int kt = 0; kt < KN; kt += 16) {
        const bool more = (kt + 16 < KN);
        if (more) {
            ea0 = *(const float4*)(pe0 + kt + 16);
            ka0 = *(const float4*)(pk0 + kt + 16);
            ea1 = *(const float4*)(pe1 + kt + 16);
            ka1 = *(const float4*)(pk1 + kt + 16);
            rb0 = *(const float4*)(pw + (size_t)(kt + 16) * Dd);
            rb1 = *(const float4*)(pw + (size_t)(kt + 16) * Dd + 4);
        }
        compute_slab(As[buf], Bs[buf], acc, lane, wm, wn);
        if (more) {
            const int nb = buf ^ 1;
            As[nb][akq + 0][ar] = f2tf(ea0.x * ka0.x); As[nb][akq + 1][ar] = f2tf(ea0.y * ka0.y);
            As[nb][akq + 2][ar] = f2tf(ea0.z * ka0.z); As[nb][akq + 3][ar] = f2tf(ea0.w * ka0.w);
            As[nb][akq + 0][ar + 64] = f2tf(ea1.x * ka1.x); As[nb][akq + 1][ar + 64] = f2tf(ea1.y * ka1.y);
            As[nb][akq + 2][ar + 64] = f2tf(ea1.z * ka1.z); As[nb][akq + 3][ar + 64] = f2tf(ea1.w * ka1.w);
            uint4 v0 = {f2tf(rb0.x), f2tf(rb0.y), f2tf(rb0.z), f2tf(rb0.w)};
            uint4 v1 = {f2tf(rb1.x), f2tf(rb1.y), f2tf(rb1.z), f2tf(rb1.w)};
            *(uint4*)&Bs[nb][bk][bn]     = v0;
            *(uint4*)&Bs[nb][bk][bn + 4] = v1;
            __syncthreads();
            buf = nb;
        }
    }

    const int grp = lane >> 2, qd = lane & 3;
    #pragma unroll
    for (int tm = 0; tm < 4; tm++) {
        #pragma unroll
        for (int tn = 0; tn < 4; tn++) {
            const int r = row0 + wm * 64 + tm * 16 + grp;
            const int c = col0 + wn * 32 + tn * 8 + qd * 2;
            const float b0 = bt[c], b1 = bt[c + 1];
            C[(size_t)r * Dd + c]           = acc[tm][tn][0] + b0;
            C[(size_t)r * Dd + c + 1]       = acc[tm][tn][1] + b1;
            C[(size_t)(r + 8) * Dd + c]     = acc[tm][tn][2] + b0;
            C[(size_t)(r + 8) * Dd + c + 1] = acc[tm][tn][3] + b1;
        }
    }
}

// ---------------------------------------------------------------------------
// Merged scores (z = st*16 + b): S[st][b,q,k] = RSCALE * <Q[b,q,:],K[b,k,:]>
// ---------------------------------------------------------------------------
__global__ __launch_bounds__(256) void tf32_scores(const float* __restrict__ Q0,
                                                   const float* __restrict__ K0,
                                                   const float* __restrict__ Q1,
                                                   const float* __restrict__ K1,
                                                   float* __restrict__ S0,
                                                   float* __restrict__ S1,
                                                   const int* __restrict__ len0,
                                                   const int* __restrict__ len1)
{
    const int z   = blockIdx.z;
    const int st  = z >> 4;
    const int b   = z & 15;
    const int q0  = blockIdx.x * 128;
    const int k0c = blockIdx.y * 128;
    const int* lens = st ? len1 : len0;
    const int L   = lens[b] + 1;
    if (k0c >= L) return;

    __shared__ uint32_t As[2][16][STR];
    __shared__ uint32_t Bs[2][16][STR];
    const int tid  = threadIdx.x;
    const int lane = tid & 31;
    const int w    = tid >> 5;
    const int wm   = w >> 2, wn = w & 3;

    const float* Qb = (st ? Q1 : Q0) + (size_t)b * Ss * Dd;
    const float* Kb = (st ? K1 : K0) + (size_t)b * Ss * Dd;
    float*       Sb = (st ? S1 : S0) + (size_t)b * Ss * Ss;

    const int ar  = tid >> 2;
    const int akq = (tid & 3) * 4;

    const float* pa0 = &Qb[(size_t)(q0 + ar) * Dd + akq];
    const float* pa1 = &Qb[(size_t)(q0 + ar + 64) * Dd + akq];
    const float* pb0 = &Kb[(size_t)(k0c + ar) * Dd + akq];
    const float* pb1 = &Kb[(size_t)(k0c + ar + 64) * Dd + akq];

    float4 ra0 = *(const float4*)pa0;
    float4 ra1 = *(const float4*)pa1;
    float4 rb0 = *(const float4*)pb0;
    float4 rb1 = *(const float4*)pb1;

    As[0][akq + 0][ar] = f2tf(ra0.x); As[0][akq + 1][ar] = f2tf(ra0.y);
    As[0][akq + 2][ar] = f2tf(ra0.z); As[0][akq + 3][ar] = f2tf(ra0.w);
    As[0][akq + 0][ar + 64] = f2tf(ra1.x); As[0][akq + 1][ar + 64] = f2tf(ra1.y);
    As[0][akq + 2][ar + 64] = f2tf(ra1.z); As[0][akq + 3][ar + 64] = f2tf(ra1.w);
    Bs[0][akq + 0][ar] = f2tf(rb0.x); Bs[0][akq + 1][ar] = f2tf(rb0.y);
    Bs[0][akq + 2][ar] = f2tf(rb0.z); Bs[0][akq + 3][ar] = f2tf(rb0.w);
    Bs[0][akq + 0][ar + 64] = f2tf(rb1.x); Bs[0][akq + 1][ar + 64] = f2tf(rb1.y);
    Bs[0][akq + 2][ar + 64] = f2tf(rb1.z); Bs[0][akq + 3][ar + 64] = f2tf(rb1.w);
    __syncthreads();

    float acc[4][4][4] = {};
    int buf = 0;
    for (int kt = 0; kt < Dd; kt += 16) {
        const bool more = (kt + 16 < Dd);
        if (more) {
            ra0 = *(const float4*)(pa0 + kt + 16);
            ra1 = *(const float4*)(pa1 + kt + 16);
            rb0 = *(const float4*)(pb0 + kt + 16);
            rb1 = *(const float4*)(pb1 + kt + 16);
        }
        compute_slab(As[buf], Bs[buf], acc, lane, wm, wn);
        if (more) {
            const int nb = buf ^ 1;
            As[nb][akq + 0][ar] = f2tf(ra0.x); As[nb][akq + 1][ar] = f2tf(ra0.y);
            As[nb][akq + 2][ar] = f2tf(ra0.z); As[nb][akq + 3][ar] = f2tf(ra0.w);
            As[nb][akq + 0][ar + 64] = f2tf(ra1.x); As[nb][akq + 1][ar + 64] = f2tf(ra1.y);
            As[nb][akq + 2][ar + 64] = f2tf(ra1.z); As[nb][akq + 3][ar + 64] = f2tf(ra1.w);
            Bs[nb][akq + 0][ar] = f2tf(rb0.x); Bs[nb][akq + 1][ar] = f2tf(rb0.y);
            Bs[nb][akq + 2][ar] = f2tf(rb0.z); Bs[nb][akq + 3][ar] = f2tf(rb0.w);
            Bs[nb][akq + 0][ar + 64] = f2tf(rb1.x); Bs[nb][akq + 1][ar + 64] = f2tf(rb1.y);
            Bs[nb][akq + 2][ar + 64] = f2tf(rb1.z); Bs[nb][akq + 3][ar + 64] = f2tf(rb1.w);
            __syncthreads();
            buf = nb;
        }
    }

    const int grp = lane >> 2, qd = lane & 3;
    #pragma unroll
    for (int tm = 0; tm < 4; tm++) {
        #pragma unroll
        for (int tn = 0; tn < 4; tn++) {
            const int q = q0 + wm * 64 + tm * 16 + grp;
            const int k = k0c + wn * 32 + tn * 8 + qd * 2;
            Sb[(size_t)q * Ss + k]           = acc[tm][tn][0] * RSCALE;
            Sb[(size_t)q * Ss + k + 1]       = acc[tm][tn][1] * RSCALE;
            Sb[(size_t)(q + 8) * Ss + k]     = acc[tm][tn][2] * RSCALE;
            Sb[(size_t)(q + 8) * Ss + k + 1] = acc[tm][tn][3] * RSCALE;
        }
    }
}

// ---------------------------------------------------------------------------
// Row stats (merged streams, no write-back): MZ = (max, 1/sum(exp(s-max)))
// grid: (Mtot, 2)
// ---------------------------------------------------------------------------
__global__ void rowstats_kernel(const float* __restrict__ S0,
                                const float* __restrict__ S1,
                                float2* __restrict__ MZ,
                                const int* __restrict__ len0,
                                const int* __restrict__ len1)
{
    __shared__ float red[256];
    const int st  = blockIdx.y;
    const int r   = blockIdx.x;
    const int b   = r / Ss;
    const int L   = (st ? len1 : len0)[b] + 1;
    const int tid = threadIdx.x;
    const float* row = (st ? S1 : S0) + (size_t)r * Ss;

    float mx = -1e30f;
    for (int k = tid; k < L; k += 256) mx = fmaxf(mx, row[k]);
    red[tid] = mx;
    __syncthreads();
    for (int s = 128; s > 0; s >>= 1) {
        if (tid < s) red[tid] = fmaxf(red[tid], red[tid + s]);
        __syncthreads();
    }
    mx = red[0];
    __syncthreads();

    float z = 0.f;
    for (int k = tid; k < L; k += 256) z += __expf(row[k] - mx);
    red[tid] = z;
    __syncthreads();
    for (int s = 128; s > 0; s >>= 1) {
        if (tid < s) red[tid] += red[tid + s];
        __syncthreads();
    }
    if (tid == 0) MZ[st * Mtot + r] = make_float2(mx, 1.0f / red[0]);
}

// ---------------------------------------------------------------------------
// Column sums (merged): c[st,b,k] = sum_q exp(s-m_q)*invZ_q.  grid (8,16,2)
// ---------------------------------------------------------------------------
__global__ void colsum_kernel(const float* __restrict__ S0,
                              const float* __restrict__ S1,
                              const float2* __restrict__ MZ,
                              float* __restrict__ c,
                              const int* __restrict__ len0,
                              const int* __restrict__ len1)
{
    const int st = blockIdx.z;
    const int b  = blockIdx.y;
    const int k  = blockIdx.x * 256 + threadIdx.x;
    const int L  = (st ? len1 : len0)[b] + 1;
    if (k >= L) { c[st * Mtot + b * Ss + k] = 0.0f; return; }

    const float* sp = (st ? S1 : S0) + (size_t)b * Ss * Ss + k;
    const float2* mz = MZ + st * Mtot + b * Ss;
    float acc = 0.f;
    #pragma unroll 1
    for (int q = 0; q < Ss; q += 4) {
        float s0 = sp[(size_t)(q + 0) * Ss];
        float s1 = sp[(size_t)(q + 1) * Ss];
        float s2 = sp[(size_t)(q + 2) * Ss];
        float s3 = sp[(size_t)(q + 3) * Ss];
        float2 m0 = mz[q + 0], m1 = mz[q + 1], m2 = mz[q + 2], m3 = mz[q + 3];
        acc += __expf(s0 - m0.x) * m0.y + __expf(s1 - m1.x) * m1.y
             + __expf(s2 - m2.x) * m2.y + __expf(s3 - m3.x) * m3.y;
    }
    c[st * Mtot + b * Ss + k] = acc;
}

// ---------------------------------------------------------------------------
// sumO[st,b,d] = sum_{k<L} c[st,b,k] * V[st][b,k,d].  grid (4,16,2)
// ---------------------------------------------------------------------------
__global__ void sumo_kernel(const float* __restrict__ c,
                            const float* __restrict__ V0,
                            const float* __restrict__ V1,
                            float* __restrict__ sumO,
                            const int* __restrict__ len0,
                            const int* __restrict__ len1)
{
    const int st = blockIdx.z;
    const int b  = blockIdx.y;
    const int d  = blockIdx.x * 128 + threadIdx.x;
    const int L  = (st ? len1 : len0)[b] + 1;
    const float* Vb = (st ? V1 : V0) + (size_t)b * Ss * Dd;
    const float* cb = c + st * Mtot + b * Ss;
    float acc = 0.f;
    #pragma unroll 4
    for (int k = 0; k < L; k++)
        acc += cb[k] * Vb[(size_t)k * Dd + d];
    sumO[st * Bb * Dd + b * Dd + d] = acc;
}

// ---------------------------------------------------------------------------
// sa[st,b,n] = sumO[st,b,:] @ Wo[st][:,n] + S * bo[st][n].  grid (2,16,2)
// ---------------------------------------------------------------------------
__global__ void sa_kernel(const float* __restrict__ sumO,
                          const float* __restrict__ Wo0,
                          const float* __restrict__ bo0,
                          const float* __restrict__ Wo1,
                          const float* __restrict__ bo1,
                          float* __restrict__ cat)
{
    __shared__ float sO[Dd];
    const int st = blockIdx.z;
    const int b  = blockIdx.y;
    const int n  = blockIdx.x * 256 + threadIdx.x;
    const float* Wo = st ? Wo1 : Wo0;
    const float* bo = st ? bo1 : bo0;
    for (int i = threadIdx.x; i < Dd; i += 256) sO[i] = sumO[st * Bb * Dd + b * Dd + i];
    __syncthreads();
    float acc = (float)Ss * bo[n];
    #pragma unroll 8
    for (int d = 0; d < Dd; d++)
        acc += sO[d] * Wo[(size_t)d * Dd + n];
    cat[b * (2 * Dd) + st * Dd + n] = acc;
}

// ---------------------------------------------------------------------------
// out[b,j] = tanh(cat[b,:] @ W_out[:,j] + b_out[j])
// ---------------------------------------------------------------------------
__global__ void final_kernel(const float* __restrict__ cat,
                             const float* __restrict__ Wout,
                             const float* __restrict__ bout,
                             float* __restrict__ out)
{
    __shared__ float sc[2 * Dd];
    const int b = blockIdx.x;
    const int j = threadIdx.x;
    for (int i = threadIdx.x; i < 2 * Dd; i += 256) sc[i] = cat[b * (2 * Dd) + i];
    __syncthreads();
    float acc = bout[j];
    #pragma unroll 8
    for (int i = 0; i < 2 * Dd; i++)
        acc += sc[i] * Wout[(size_t)i * KN + j];
    out[b * KN + j] = tanhf(acc);
}

// ---------------------------------------------------------------------------
// Launch
// ---------------------------------------------------------------------------
extern "C" void kernel_launch(void* const* d_in, const int* in_sizes, int n_in,
                              void* d_out, int out_size)
{
    const int*   data0 = (const int*)  d_in[0];
    const float* know0 = (const float*)d_in[1];
    const int*   len0  = (const int*)  d_in[2];
    const int*   data1 = (const int*)  d_in[3];
    const float* know1 = (const float*)d_in[4];
    const int*   len1  = (const int*)  d_in[5];
    const float* emb   = (const float*)d_in[6];
    const float* Wt    = (const float*)d_in[7];
    const float* bt    = (const float*)d_in[8];
    const float* Wq[2] = {(const float*)d_in[9],  (const float*)d_in[17]};
    const float* bq[2] = {(const float*)d_in[10], (const float*)d_in[18]};
    const float* Wk[2] = {(const float*)d_in[11], (const float*)d_in[19]};
    const float* bk[2] = {(const float*)d_in[12], (const float*)d_in[20]};
    const float* Wv[2] = {(const float*)d_in[13], (const float*)d_in[21]};
    const float* bv[2] = {(const float*)d_in[14], (const float*)d_in[22]};
    const float* Wo[2] = {(const float*)d_in[15], (const float*)d_in[23]};
    const float* bo[2] = {(const float*)d_in[16], (const float*)d_in[24]};
    const float* Wout  = (const float*)d_in[25];
    const float* bout  = (const float*)d_in[26];
    float* out = (float*)d_out;

    float *pX, *pQ, *pK, *pV, *pS, *pC, *pSO, *pCat;
    float2* pMZ;
    cudaGetSymbolAddress((void**)&pX,   g_X);
    cudaGetSymbolAddress((void**)&pQ,   g_Q);
    cudaGetSymbolAddress((void**)&pK,   g_K);
    cudaGetSymbolAddress((void**)&pV,   g_V);
    cudaGetSymbolAddress((void**)&pS,   g_S);
    cudaGetSymbolAddress((void**)&pMZ,  g_MZ);
    cudaGetSymbolAddress((void**)&pC,   g_c);
    cudaGetSymbolAddress((void**)&pSO,  g_sumO);
    cudaGetSymbolAddress((void**)&pCat, g_cat);

    const size_t SD = (size_t)Mtot * Dd;       // per-stream X/Q/K/V stride
    const size_t SS = (size_t)67108864;        // per-stream S stride
    float* X[2] = {pX, pX + SD};
    float* Q[2] = {pQ, pQ + SD};
    float* K[2] = {pK, pK + SD};
    float* V[2] = {pV, pV + SD};
    float* S[2] = {pS, pS + SS};

    QKVArgs qa;
    for (int st = 0; st < 2; st++) {
        qa.W[st * 3 + 0] = Wq[st]; qa.bias[st * 3 + 0] = bq[st]; qa.C[st * 3 + 0] = Q[st];
        qa.W[st * 3 + 1] = Wk[st]; qa.bias[st * 3 + 1] = bk[st]; qa.C[st * 3 + 1] = K[st];
        qa.W[st * 3 + 2] = Wv[st]; qa.bias[st * 3 + 2] = bv[st]; qa.C[st * 3 + 2] = V[st];
        qa.A[st] = X[st];
    }
    qa.lens[0] = len0; qa.lens[1] = len1;

    const dim3 gEmbed(Mtot / 128, Dd / 128, 2);      // 256 x 4 x 2
    const dim3 gQKV  (Mtot / 128, Dd / 128, 6);      // 256 x 4 x 6
    const dim3 gScore(Ss / 128, Ss / 128, 32);       // 16 x 16 x 32

    tf32_embed<<<gEmbed, 256>>>(data0, know0, data1, know1, emb, Wt, bt, X[0], X[1]);
    tf32_qkv<<<gQKV, 256>>>(qa);
    tf32_scores<<<gScore, 256>>>(Q[0], K[0], Q[1], K[1], S[0], S[1], len0, len1);
    rowstats_kernel<<<dim3(Mtot, 2), 256>>>(S[0], S[1], pMZ, len0, len1);
    colsum_kernel<<<dim3(Ss / 256, Bb, 2), 256>>>(S[0], S[1], pMZ, pC, len0, len1);
    sumo_kernel<<<dim3(Dd / 128, Bb, 2), 128>>>(pC, V[0], V[1], pSO, len0, len1);
    sa_kernel<<<dim3(Dd / 256, Bb, 2), 256>>>(pSO, Wo[0], bo[0], Wo[1], bo[1], pCat);
    final_kernel<<<Bb, 256>>>(pCat, Wout, bout, out);
}

// round 13
// speedup vs baseline: 1.7517x; 1.0552x over previous
#include <cuda_runtime.h>
#include <math.h>
#include <stdint.h>

// Problem constants
#define Bb   16
#define Ss   2048
#define KN   256
#define Dd   512
#define Mtot (Bb * Ss)
#define RSCALE 0.044194173824159216f

#define STR 136   // smem row stride (words)

// ---------------------------------------------------------------------------
// Scratch (per-stream where needed)
// ---------------------------------------------------------------------------
__device__ float g_X[2][Mtot * Dd];
__device__ float g_Q[2][Mtot * Dd];
__device__ float g_K[2][Mtot * Dd];
__device__ float g_V[2][Mtot * Dd];
__device__ float g_S[2][67108864];          // 2 x 256 MB scores [B,S,S]
__device__ float2 g_MZp[2 * Bb * 16 * Ss];  // per-(row,ktile) partial (max, sumexp)
__device__ float2 g_MZ[2 * Mtot];           // per-row (max, invZ)
__device__ float g_c[2 * Mtot];
__device__ float g_sumO[2 * Bb * Dd];
__device__ float g_cat[Bb * 2 * Dd];

// ---------------------------------------------------------------------------
// tf32 helpers (R6-proven core)
// ---------------------------------------------------------------------------
__device__ __forceinline__ uint32_t f2tf(float f) {
    uint32_t r;
    asm("cvt.rna.tf32.f32 %0, %1;" : "=r"(r) : "f"(f));
    return r;
}

__device__ __forceinline__ void mma8(float c[4], const uint32_t a[4], const uint32_t b[2]) {
    asm volatile(
        "mma.sync.aligned.m16n8k8.row.col.f32.tf32.tf32.f32 "
        "{%0,%1,%2,%3}, {%4,%5,%6,%7}, {%8,%9}, {%0,%1,%2,%3};"
        : "+f"(c[0]), "+f"(c[1]), "+f"(c[2]), "+f"(c[3])
        : "r"(a[0]), "r"(a[1]), "r"(a[2]), "r"(a[3]), "r"(b[0]), "r"(b[1]));
}

// Warp computes a 64(M) x 32(N) subtile of the 128x128 CTA tile.
__device__ __forceinline__ void compute_slab(const uint32_t As[16][STR],
                                             const uint32_t Bs[16][STR],
                                             float acc[4][4][4],
                                             int lane, int wm, int wn)
{
    const int grp = lane >> 2;
    const int qd  = lane & 3;
    const int mb0 = wm * 64;
    const int nb0 = wn * 32;
    #pragma unroll
    for (int ks = 0; ks < 2; ks++) {
        const int k0 = ks * 8;
        uint32_t a[4][4], b[4][2];
        #pragma unroll
        for (int tm = 0; tm < 4; tm++) {
            const int m = mb0 + tm * 16 + grp;
            a[tm][0] = As[k0 + qd][m];
            a[tm][1] = As[k0 + qd][m + 8];
            a[tm][2] = As[k0 + qd + 4][m];
            a[tm][3] = As[k0 + qd + 4][m + 8];
        }
        #pragma unroll
        for (int tn = 0; tn < 4; tn++) {
            const int n = nb0 + tn * 8 + grp;
            b[tn][0] = Bs[k0 + qd][n];
            b[tn][1] = Bs[k0 + qd + 4][n];
        }
        #pragma unroll
        for (int tm = 0; tm < 4; tm++)
            #pragma unroll
            for (int tn = 0; tn < 4; tn++)
                mma8(acc[tm][tn], a[tm], b[tn]);
    }
}

// ---------------------------------------------------------------------------
// Args for the merged Q/K/V GEMM launch
// ---------------------------------------------------------------------------
struct QKVArgs {
    const float* W[6];      // Wq0,Wk0,Wv0,Wq1,Wk1,Wv1   ([K][N] row-major)
    const float* bias[6];
    float*       C[6];      // Q0,K0,V0,Q1,K1,V1
    const float* A[2];      // X0, X1
    const int*   lens[2];
};

// ---------------------------------------------------------------------------
// Merged Q/K/V GEMM: z = st*3 + op.  C = A @ W + bias.  K,V skip masked rows.
// ---------------------------------------------------------------------------
__global__ __launch_bounds__(256) void tf32_qkv(QKVArgs args)
{
    __shared__ uint32_t As[2][16][STR];
    __shared__ uint32_t Bs[2][16][STR];
    const int z    = blockIdx.z;
    const int st   = (z >= 3) ? 1 : 0;
    const int op   = z - st * 3;
    const int tid  = threadIdx.x;
    const int lane = tid & 31;
    const int w    = tid >> 5;
    const int wm   = w >> 2, wn = w & 3;
    const int row0 = blockIdx.x * 128;
    const int col0 = blockIdx.y * 128;

    if (op != 0) {   // K, V: masked row-tiles
        const int L = args.lens[st][row0 / Ss] + 1;
        if ((row0 % Ss) >= L) return;
    }

    const float* A    = args.A[st];
    const float* W    = args.W[z];
    const float* bias = args.bias[z];
    float*       C    = args.C[z];

    const int ar  = tid >> 2;
    const int akq = (tid & 3) * 4;
    const int bk  = tid >> 4;
    const int bn  = (tid & 15) * 8;

    const float* pa0 = &A[(size_t)(row0 + ar) * Dd + akq];
    const float* pa1 = &A[(size_t)(row0 + ar + 64) * Dd + akq];
    const float* pw  = &W[(size_t)bk * Dd + col0 + bn];

    float4 ra0 = *(const float4*)pa0;
    float4 ra1 = *(const float4*)pa1;
    float4 rb0 = *(const float4*)pw;
    float4 rb1 = *(const float4*)(pw + 4);

    As[0][akq + 0][ar] = f2tf(ra0.x); As[0][akq + 1][ar] = f2tf(ra0.y);
    As[0][akq + 2][ar] = f2tf(ra0.z); As[0][akq + 3][ar] = f2tf(ra0.w);
    As[0][akq + 0][ar + 64] = f2tf(ra1.x); As[0][akq + 1][ar + 64] = f2tf(ra1.y);
    As[0][akq + 2][ar + 64] = f2tf(ra1.z); As[0][akq + 3][ar + 64] = f2tf(ra1.w);
    {
        uint4 v0 = {f2tf(rb0.x), f2tf(rb0.y), f2tf(rb0.z), f2tf(rb0.w)};
        uint4 v1 = {f2tf(rb1.x), f2tf(rb1.y), f2tf(rb1.z), f2tf(rb1.w)};
        *(uint4*)&Bs[0][bk][bn]     = v0;
        *(uint4*)&Bs[0][bk][bn + 4] = v1;
    }
    __syncthreads();

    float acc[4][4][4] = {};
    int buf = 0;
    for (int kt = 0; kt < Dd; kt += 16) {
        const bool more = (kt + 16 < Dd);
        if (more) {
            ra0 = *(const float4*)(pa0 + kt + 16);
            ra1 = *(const float4*)(pa1 + kt + 16);
            rb0 = *(const float4*)(pw + (size_t)(kt + 16) * Dd);
            rb1 = *(const float4*)(pw + (size_t)(kt + 16) * Dd + 4);
        }
        compute_slab(As[buf], Bs[buf], acc, lane, wm, wn);
        if (more) {
            const int nb = buf ^ 1;
            As[nb][akq + 0][ar] = f2tf(ra0.x); As[nb][akq + 1][ar] = f2tf(ra0.y);
            As[nb][akq + 2][ar] = f2tf(ra0.z); As[nb][akq + 3][ar] = f2tf(ra0.w);
            As[nb][akq + 0][ar + 64] = f2tf(ra1.x); As[nb][akq + 1][ar + 64] = f2tf(ra1.y);
            As[nb][akq + 2][ar + 64] = f2tf(ra1.z); As[nb][akq + 3][ar + 64] = f2tf(ra1.w);
            uint4 v0 = {f2tf(rb0.x), f2tf(rb0.y), f2tf(rb0.z), f2tf(rb0.w)};
            uint4 v1 = {f2tf(rb1.x), f2tf(rb1.y), f2tf(rb1.z), f2tf(rb1.w)};
            *(uint4*)&Bs[nb][bk][bn]     = v0;
            *(uint4*)&Bs[nb][bk][bn + 4] = v1;
            __syncthreads();
            buf = nb;
        }
    }

    const int grp = lane >> 2, qd = lane & 3;
    #pragma unroll
    for (int tm = 0; tm < 4; tm++) {
        #pragma unroll
        for (int tn = 0; tn < 4; tn++) {
            const int r = row0 + wm * 64 + tm * 16 + grp;
            const int c = col0 + wn * 32 + tn * 8 + qd * 2;
            const float b0 = bias[c], b1 = bias[c + 1];
            C[(size_t)r * Dd + c]           = acc[tm][tn][0] + b0;
            C[(size_t)r * Dd + c + 1]       = acc[tm][tn][1] + b1;
            C[(size_t)(r + 8) * Dd + c]     = acc[tm][tn][2] + b0;
            C[(size_t)(r + 8) * Dd + c + 1] = acc[tm][tn][3] + b1;
        }
    }
}

// ---------------------------------------------------------------------------
// Merged embed GEMM (z = stream): X[st] = (emb[data]*know) @ W_t + b_t
// ---------------------------------------------------------------------------
__global__ __launch_bounds__(256) void tf32_embed(const int* __restrict__ d0,
                                                  const float* __restrict__ kn0,
                                                  const int* __restrict__ d1,
                                                  const float* __restrict__ kn1,
                                                  const float* __restrict__ emb,
                                                  const float* __restrict__ Wt,
                                                  const float* __restrict__ bt,
                                                  float* __restrict__ X0,
                                                  float* __restrict__ X1)
{
    __shared__ uint32_t As[2][16][STR];
    __shared__ uint32_t Bs[2][16][STR];
    __shared__ int sIdx[128];
    const int st   = blockIdx.z;
    const int* data = st ? d1 : d0;
    const float* know = st ? kn1 : kn0;
    float* C = st ? X1 : X0;

    const int tid  = threadIdx.x;
    const int lane = tid & 31;
    const int w    = tid >> 5;
    const int wm   = w >> 2, wn = w & 3;
    const int row0 = blockIdx.x * 128;
    const int col0 = blockIdx.y * 128;

    if (tid < 128) sIdx[tid] = data[row0 + tid];
    __syncthreads();

    const int ar  = tid >> 2;
    const int akq = (tid & 3) * 4;
    const int bk  = tid >> 4;
    const int bn  = (tid & 15) * 8;

    const float* pe0 = &emb[(size_t)sIdx[ar] * KN + akq];
    const float* pe1 = &emb[(size_t)sIdx[ar + 64] * KN + akq];
    const float* pk0 = &know[(size_t)(row0 + ar) * KN + akq];
    const float* pk1 = &know[(size_t)(row0 + ar + 64) * KN + akq];
    const float* pw  = &Wt[(size_t)bk * Dd + col0 + bn];

    float4 ea0 = *(const float4*)pe0;
    float4 ka0 = *(const float4*)pk0;
    float4 ea1 = *(const float4*)pe1;
    float4 ka1 = *(const float4*)pk1;
    float4 rb0 = *(const float4*)pw;
    float4 rb1 = *(const float4*)(pw + 4);

    As[0][akq + 0][ar] = f2tf(ea0.x * ka0.x); As[0][akq + 1][ar] = f2tf(ea0.y * ka0.y);
    As[0][akq + 2][ar] = f2tf(ea0.z * ka0.z); As[0][akq + 3][ar] = f2tf(ea0.w * ka0.w);
    As[0][akq + 0][ar + 64] = f2tf(ea1.x * ka1.x); As[0][akq + 1][ar + 64] = f2tf(ea1.y * ka1.y);
    As[0][akq + 2][ar + 64] = f2tf(ea1.z * ka1.z); As[0][akq + 3][ar + 64] = f2tf(ea1.w * ka1.w);
    {
        uint4 v0 = {f2tf(rb0.x), f2tf(rb0.y), f2tf(rb0.z), f2tf(rb0.w)};
        uint4 v1 = {f2tf(rb1.x), f2tf(rb1.y), f2tf(rb1.z), f2tf(rb1.w)};
        *(uint4*)&Bs[0][bk][bn]     = v0;
        *(uint4*)&Bs[0][bk][bn + 4] = v1;
    }
    __syncthreads();

    float acc[4][4][4] = {};
    int buf = 0;
    for (int kt = 0; kt < KN; kt += 16) {
        const bool more = (kt + 16 < KN);
        if (more) {
            ea0 = *(const float4*)(pe0 + kt + 16);
            ka0 = *(const float4*)(pk0 + kt + 16);
            ea1 = *(const float4*)(pe1 + kt + 16);
            ka1 = *(const float4*)(pk1 + kt + 16);
            rb0 = *(const float4*)(pw + (size_t)(kt + 16) * Dd);
            rb1 = *(const float4*)(pw + (size_t)(kt + 16) * Dd + 4);
        }
        compute_slab(As[buf], Bs[buf], acc, lane, wm, wn);
        if (more) {
            const int nb = buf ^ 1;
            As[nb][akq + 0][ar] = f2tf(ea0.x * ka0.x); As[nb][akq + 1][ar] = f2tf(ea0.y * ka0.y);
            As[nb][akq + 2][ar] = f2tf(ea0.z * ka0.z); As[nb][akq + 3][ar] = f2tf(ea0.w * ka0.w);
            As[nb][akq + 0][ar + 64] = f2tf(ea1.x * ka1.x); As[nb][akq + 1][ar + 64] = f2tf(ea1.y * ka1.y);
            As[nb][akq + 2][ar + 64] = f2tf(ea1.z * ka1.z); As[nb][akq + 3][ar + 64] = f2tf(ea1.w * ka1.w);
            uint4 v0 = {f2tf(rb0.x), f2tf(rb0.y), f2tf(rb0.z), f2tf(rb0.w)};
            uint4 v1 = {f2tf(rb1.x), f2tf(rb1.y), f2tf(rb1.z), f2tf(rb1.w)};
            *(uint4*)&Bs[nb][bk][bn]     = v0;
            *(uint4*)&Bs[nb][bk][bn + 4] = v1;
            __syncthreads();
            buf = nb;
        }
    }

    const int grp = lane >> 2, qd = lane & 3;
    #pragma unroll
    for (int tm = 0; tm < 4; tm++) {
        #pragma unroll
        for (int tn = 0; tn < 4; tn++) {
            const int r = row0 + wm * 64 + tm * 16 + grp;
            const int c = col0 + wn * 32 + tn * 8 + qd * 2;
            const float b0 = bt[c], b1 = bt[c + 1];
            C[(size_t)r * Dd + c]           = acc[tm][tn][0] + b0;
            C[(size_t)r * Dd + c + 1]       = acc[tm][tn][1] + b1;
            C[(size_t)(r + 8) * Dd + c]     = acc[tm][tn][2] + b0;
            C[(size_t)(r + 8) * Dd + c + 1] = acc[tm][tn][3] + b1;
        }
    }
}

// ---------------------------------------------------------------------------
// Merged scores (z = st*16 + b): S = RSCALE * Q K^T, PLUS fused per-row
// tile-local softmax partials (max, sumexp over this 128-k tile, cols < L).
// Partials: g_MZp[((st*16+b)*16 + ktile)*Ss + q]
// ---------------------------------------------------------------------------
__global__ __launch_bounds__(256) void tf32_scores(const float* __restrict__ Q0,
                                                   const float* __restrict__ K0,
                                                   const float* __restrict__ Q1,
                                                   const float* __restrict__ K1,
                                                   float* __restrict__ S0,
                                                   float* __restrict__ S1,
                                                   float2* __restrict__ MZp,
                                                   const int* __restrict__ len0,
                                                   const int* __restrict__ len1)
{
    const int z   = blockIdx.z;
    const int st  = z >> 4;
    const int b   = z & 15;
    const int q0  = blockIdx.x * 128;
    const int k0c = blockIdx.y * 128;
    const int* lens = st ? len1 : len0;
    const int L   = lens[b] + 1;
    if (k0c >= L) return;

    __shared__ uint32_t As[2][16][STR];
    __shared__ uint32_t Bs[2][16][STR];
    __shared__ float sRed[128][4];
    const int tid  = threadIdx.x;
    const int lane = tid & 31;
    const int w    = tid >> 5;
    const int wm   = w >> 2, wn = w & 3;

    const float* Qb = (st ? Q1 : Q0) + (size_t)b * Ss * Dd;
    const float* Kb = (st ? K1 : K0) + (size_t)b * Ss * Dd;
    float*       Sb = (st ? S1 : S0) + (size_t)b * Ss * Ss;

    const int ar  = tid >> 2;
    const int akq = (tid & 3) * 4;

    const float* pa0 = &Qb[(size_t)(q0 + ar) * Dd + akq];
    const float* pa1 = &Qb[(size_t)(q0 + ar + 64) * Dd + akq];
    const float* pb0 = &Kb[(size_t)(k0c + ar) * Dd + akq];
    const float* pb1 = &Kb[(size_t)(k0c + ar + 64) * Dd + akq];

    float4 ra0 = *(const float4*)pa0;
    float4 ra1 = *(const float4*)pa1;
    float4 rb0 = *(const float4*)pb0;
    float4 rb1 = *(const float4*)pb1;

    As[0][akq + 0][ar] = f2tf(ra0.x); As[0][akq + 1][ar] = f2tf(ra0.y);
    As[0][akq + 2][ar] = f2tf(ra0.z); As[0][akq + 3][ar] = f2tf(ra0.w);
    As[0][akq + 0][ar + 64] = f2tf(ra1.x); As[0][akq + 1][ar + 64] = f2tf(ra1.y);
    As[0][akq + 2][ar + 64] = f2tf(ra1.z); As[0][akq + 3][ar + 64] = f2tf(ra1.w);
    Bs[0][akq + 0][ar] = f2tf(rb0.x); Bs[0][akq + 1][ar] = f2tf(rb0.y);
    Bs[0][akq + 2][ar] = f2tf(rb0.z); Bs[0][akq + 3][ar] = f2tf(rb0.w);
    Bs[0][akq + 0][ar + 64] = f2tf(rb1.x); Bs[0][akq + 1][ar + 64] = f2tf(rb1.y);
    Bs[0][akq + 2][ar + 64] = f2tf(rb1.z); Bs[0][akq + 3][ar + 64] = f2tf(rb1.w);
    __syncthreads();

    float acc[4][4][4] = {};
    int buf = 0;
    for (int kt = 0; kt < Dd; kt += 16) {
        const bool more = (kt + 16 < Dd);
        if (more) {
            ra0 = *(const float4*)(pa0 + kt + 16);
            ra1 = *(const float4*)(pa1 + kt + 16);
            rb0 = *(const float4*)(pb0 + kt + 16);
            rb1 = *(const float4*)(pb1 + kt + 16);
        }
        compute_slab(As[buf], Bs[buf], acc, lane, wm, wn);
        if (more) {
            const int nb = buf ^ 1;
            As[nb][akq + 0][ar] = f2tf(ra0.x); As[nb][akq + 1][ar] = f2tf(ra0.y);
            As[nb][akq + 2][ar] = f2tf(ra0.z); As[nb][akq + 3][ar] = f2tf(ra0.w);
            As[nb][akq + 0][ar + 64] = f2tf(ra1.x); As[nb][akq + 1][ar + 64] = f2tf(ra1.y);
            As[nb][akq + 2][ar + 64] = f2tf(ra1.z); As[nb][akq + 3][ar + 64] = f2tf(ra1.w);
            Bs[nb][akq + 0][ar] = f2tf(rb0.x); Bs[nb][akq + 1][ar] = f2tf(rb0.y);
            Bs[nb][akq + 2][ar] = f2tf(rb0.z); Bs[nb][akq + 3][ar] = f2tf(rb0.w);
            Bs[nb][akq + 0][ar + 64] = f2tf(rb1.x); Bs[nb][akq + 1][ar + 64] = f2tf(rb1.y);
            Bs[nb][akq + 2][ar + 64] = f2tf(rb1.z); Bs[nb][akq + 3][ar + 64] = f2tf(rb1.w);
            __syncthreads();
            buf = nb;
        }
    }

    const int grp = lane >> 2, qd = lane & 3;

    // store S tile
    #pragma unroll
    for (int tm = 0; tm < 4; tm++) {
        #pragma unroll
        for (int tn = 0; tn < 4; tn++) {
            const int q = q0 + wm * 64 + tm * 16 + grp;
            const int k = k0c + wn * 32 + tn * 8 + qd * 2;
            Sb[(size_t)q * Ss + k]           = acc[tm][tn][0] * RSCALE;
            Sb[(size_t)q * Ss + k + 1]       = acc[tm][tn][1] * RSCALE;
            Sb[(size_t)(q + 8) * Ss + k]     = acc[tm][tn][2] * RSCALE;
            Sb[(size_t)(q + 8) * Ss + k + 1] = acc[tm][tn][3] * RSCALE;
        }
    }

    // ---- fused per-row tile stats (cols < L only) ----
    // phase 1: row max
    float rmax[4][2];
    #pragma unroll
    for (int tm = 0; tm < 4; tm++) {
        #pragma unroll
        for (int h = 0; h < 2; h++) {
            float m = -1e30f;
            #pragma unroll
            for (int tn = 0; tn < 4; tn++) {
                const int k = k0c + wn * 32 + tn * 8 + qd * 2;
                const float v0 = acc[tm][tn][h * 2 + 0] * RSCALE;
                const float v1 = acc[tm][tn][h * 2 + 1] * RSCALE;
                if (k < L)     m = fmaxf(m, v0);
                if (k + 1 < L) m = fmaxf(m, v1);
            }
            m = fmaxf(m, __shfl_xor_sync(0xffffffffu, m, 1));
            m = fmaxf(m, __shfl_xor_sync(0xffffffffu, m, 2));
            rmax[tm][h] = m;
        }
    }
    if (qd == 0) {
        #pragma unroll
        for (int tm = 0; tm < 4; tm++)
            #pragma unroll
            for (int h = 0; h < 2; h++)
                sRed[wm * 64 + tm * 16 + h * 8 + grp][wn] = rmax[tm][h];
    }
    __syncthreads();
    float fmx[4][2];
    #pragma unroll
    for (int tm = 0; tm < 4; tm++) {
        #pragma unroll
        for (int h = 0; h < 2; h++) {
            const int row = wm * 64 + tm * 16 + h * 8 + grp;
            fmx[tm][h] = fmaxf(fmaxf(sRed[row][0], sRed[row][1]),
                               fmaxf(sRed[row][2], sRed[row][3]));
        }
    }
    __syncthreads();
    // phase 2: sum exp
    float rz[4][2];
    #pragma unroll
    for (int tm = 0; tm < 4; tm++) {
        #pragma unroll
        for (int h = 0; h < 2; h++) {
            float zv = 0.f;
            #pragma unroll
            for (int tn = 0; tn < 4; tn++) {
                const int k = k0c + wn * 32 + tn * 8 + qd * 2;
                const float v0 = acc[tm][tn][h * 2 + 0] * RSCALE;
                const float v1 = acc[tm][tn][h * 2 + 1] * RSCALE;
                if (k < L)     zv += __expf(v0 - fmx[tm][h]);
                if (k + 1 < L) zv += __expf(v1 - fmx[tm][h]);
            }
            zv += __shfl_xor_sync(0xffffffffu, zv, 1);
            zv += __shfl_xor_sync(0xffffffffu, zv, 2);
            rz[tm][h] = zv;
        }
    }
    if (qd == 0) {
        #pragma unroll
        for (int tm = 0; tm < 4; tm++)
            #pragma unroll
            for (int h = 0; h < 2; h++)
                sRed[wm * 64 + tm * 16 + h * 8 + grp][wn] = rz[tm][h];
    }
    __syncthreads();
    if (wn == 0 && qd == 0) {
        float2* mzp = MZp + ((size_t)z * 16 + blockIdx.y) * Ss;
        #pragma unroll
        for (int tm = 0; tm < 4; tm++) {
            #pragma unroll
            for (int h = 0; h < 2; h++) {
                const int row = wm * 64 + tm * 16 + h * 8 + grp;
                const float zz = sRed[row][0] + sRed[row][1] + sRed[row][2] + sRed[row][3];
                mzp[q0 + row] = make_float2(fmx[tm][h], zz);
            }
        }
    }
}

// ---------------------------------------------------------------------------
// Combine partial stats: MZ[st,r] = (m, 1/Z), Z = sum_t z_t * exp(m_t - m)
// grid (Ss/256, Bb, 2)
// ---------------------------------------------------------------------------
__global__ void combine_kernel(const float2* __restrict__ MZp,
                               float2* __restrict__ MZ,
                               const int* __restrict__ len0,
                               const int* __restrict__ len1)
{
    const int st = blockIdx.z;
    const int b  = blockIdx.y;
    const int q  = blockIdx.x * 256 + threadIdx.x;
    const int L  = (st ? len1 : len0)[b] + 1;
    const int nkt = (L + 127) >> 7;

    const float2* mzp = MZp + ((size_t)(st * 16 + b) * 16) * Ss + q;
    float m = -1e30f;
    for (int kt = 0; kt < nkt; kt++) m = fmaxf(m, mzp[(size_t)kt * Ss].x);
    float zsum = 0.f;
    for (int kt = 0; kt < nkt; kt++) {
        const float2 p = mzp[(size_t)kt * Ss];
        zsum += p.y * __expf(p.x - m);
    }
    MZ[st * Mtot + b * Ss + q] = make_float2(m, 1.0f / zsum);
}

// ---------------------------------------------------------------------------
// Column sums: c[st,b,k] = sum_q exp(s-m_q)*invZ_q.  grid (8,16,2)
// ---------------------------------------------------------------------------
__global__ void colsum_kernel(const float* __restrict__ S0,
                              const float* __restrict__ S1,
                              const float2* __restrict__ MZ,
                              float* __restrict__ c,
                              const int* __restrict__ len0,
                              const int* __restrict__ len1)
{
    const int st = blockIdx.z;
    const int b  = blockIdx.y;
    const int k  = blockIdx.x * 256 + threadIdx.x;
    const int L  = (st ? len1 : len0)[b] + 1;
    if (k >= L) { c[st * Mtot + b * Ss + k] = 0.0f; return; }

    const float* sp = (st ? S1 : S0) + (size_t)b * Ss * Ss + k;
    const float2* mz = MZ + st * Mtot + b * Ss;
    float acc = 0.f;
    #pragma unroll 1
    for (int q = 0; q < Ss; q += 4) {
        float s0 = sp[(size_t)(q + 0) * Ss];
        float s1 = sp[(size_t)(q + 1) * Ss];
        float s2 = sp[(size_t)(q + 2) * Ss];
        float s3 = sp[(size_t)(q + 3) * Ss];
        float2 m0 = mz[q + 0], m1 = mz[q + 1], m2 = mz[q + 2], m3 = mz[q + 3];
        acc += __expf(s0 - m0.x) * m0.y + __expf(s1 - m1.x) * m1.y
             + __expf(s2 - m2.x) * m2.y + __expf(s3 - m3.x) * m3.y;
    }
    c[st * Mtot + b * Ss + k] = acc;
}

// ---------------------------------------------------------------------------
// sumO[st,b,d] = sum_{k<L} c[st,b,k] * V[st][b,k,d].  grid (4,16,2)
// ---------------------------------------------------------------------------
__global__ void sumo_kernel(const float* __restrict__ c,
                            const float* __restrict__ V0,
                            const float* __restrict__ V1,
                            float* __restrict__ sumO,
                            const int* __restrict__ len0,
                            const int* __restrict__ len1)
{
    const int st = blockIdx.z;
    const int b  = blockIdx.y;
    const int d  = blockIdx.x * 128 + threadIdx.x;
    const int L  = (st ? len1 : len0)[b] + 1;
    const float* Vb = (st ? V1 : V0) + (size_t)b * Ss * Dd;
    const float* cb = c + st * Mtot + b * Ss;
    float acc = 0.f;
    #pragma unroll 4
    for (int k = 0; k < L; k++)
        acc += cb[k] * Vb[(size_t)k * Dd + d];
    sumO[st * Bb * Dd + b * Dd + d] = acc;
}

// ---------------------------------------------------------------------------
// sa[st,b,n] = sumO[st,b,:] @ Wo[st][:,n] + S * bo[st][n].  grid (2,16,2)
// ---------------------------------------------------------------------------
__global__ void sa_kernel(const float* __restrict__ sumO,
                          const float* __restrict__ Wo0,
                          const float* __restrict__ bo0,
                          const float* __restrict__ Wo1,
                          const float* __restrict__ bo1,
                          float* __restrict__ cat)
{
    __shared__ float sO[Dd];
    const int st = blockIdx.z;
    const int b  = blockIdx.y;
    const int n  = blockIdx.x * 256 + threadIdx.x;
    const float* Wo = st ? Wo1 : Wo0;
    const float* bo = st ? bo1 : bo0;
    for (int i = threadIdx.x; i < Dd; i += 256) sO[i] = sumO[st * Bb * Dd + b * Dd + i];
    __syncthreads();
    float acc = (float)Ss * bo[n];
    #pragma unroll 8
    for (int d = 0; d < Dd; d++)
        acc += sO[d] * Wo[(size_t)d * Dd + n];
    cat[b * (2 * Dd) + st * Dd + n] = acc;
}

// ---------------------------------------------------------------------------
// out[b,j] = tanh(cat[b,:] @ W_out[:,j] + b_out[j])
// ---------------------------------------------------------------------------
__global__ void final_kernel(const float* __restrict__ cat,
                             const float* __restrict__ Wout,
                             const float* __restrict__ bout,
                             float* __restrict__ out)
{
    __shared__ float sc[2 * Dd];
    const int b = blockIdx.x;
    const int j = threadIdx.x;
    for (int i = threadIdx.x; i < 2 * Dd; i += 256) sc[i] = cat[b * (2 * Dd) + i];
    __syncthreads();
    float acc = bout[j];
    #pragma unroll 8
    for (int i = 0; i < 2 * Dd; i++)
        acc += sc[i] * Wout[(size_t)i * KN + j];
    out[b * KN + j] = tanhf(acc);
}

// ---------------------------------------------------------------------------
// Launch
// ---------------------------------------------------------------------------
extern "C" void kernel_launch(void* const* d_in, const int* in_sizes, int n_in,
                              void* d_out, int out_size)
{
    const int*   data0 = (const int*)  d_in[0];
    const float* know0 = (const float*)d_in[1];
    const int*   len0  = (const int*)  d_in[2];
    const int*   data1 = (const int*)  d_in[3];
    const float* know1 = (const float*)d_in[4];
    const int*   len1  = (const int*)  d_in[5];
    const float* emb   = (const float*)d_in[6];
    const float* Wt    = (const float*)d_in[7];
    const float* bt    = (const float*)d_in[8];
    const float* Wq[2] = {(const float*)d_in[9],  (const float*)d_in[17]};
    const float* bq[2] = {(const float*)d_in[10], (const float*)d_in[18]};
    const float* Wk[2] = {(const float*)d_in[11], (const float*)d_in[19]};
    const float* bk[2] = {(const float*)d_in[12], (const float*)d_in[20]};
    const float* Wv[2] = {(const float*)d_in[14 - 1], (const float*)d_in[21]};
    const float* bv[2] = {(const float*)d_in[14], (const float*)d_in[22]};
    const float* Wo[2] = {(const float*)d_in[15], (const float*)d_in[23]};
    const float* bo[2] = {(const float*)d_in[16], (const float*)d_in[24]};
    const float* Wout  = (const float*)d_in[25];
    const float* bout  = (const float*)d_in[26];
    float* out = (float*)d_out;

    float *pX, *pQ, *pK, *pV, *pS, *pC, *pSO, *pCat;
    float2 *pMZ, *pMZp;
    cudaGetSymbolAddress((void**)&pX,   g_X);
    cudaGetSymbolAddress((void**)&pQ,   g_Q);
    cudaGetSymbolAddress((void**)&pK,   g_K);
    cudaGetSymbolAddress((void**)&pV,   g_V);
    cudaGetSymbolAddress((void**)&pS,   g_S);
    cudaGetSymbolAddress((void**)&pMZ,  g_MZ);
    cudaGetSymbolAddress((void**)&pMZp, g_MZp);
    cudaGetSymbolAddress((void**)&pC,   g_c);
    cudaGetSymbolAddress((void**)&pSO,  g_sumO);
    cudaGetSymbolAddress((void**)&pCat, g_cat);

    const size_t SD = (size_t)Mtot * Dd;       // per-stream X/Q/K/V stride
    const size_t SS = (size_t)67108864;        // per-stream S stride
    float* X[2] = {pX, pX + SD};
    float* Q[2] = {pQ, pQ + SD};
    float* K[2] = {pK, pK + SD};
    float* V[2] = {pV, pV + SD};
    float* S[2] = {pS, pS + SS};

    QKVArgs qa;
    for (int st = 0; st < 2; st++) {
        qa.W[st * 3 + 0] = Wq[st]; qa.bias[st * 3 + 0] = bq[st]; qa.C[st * 3 + 0] = Q[st];
        qa.W[st * 3 + 1] = Wk[st]; qa.bias[st * 3 + 1] = bk[st]; qa.C[st * 3 + 1] = K[st];
        qa.W[st * 3 + 2] = Wv[st]; qa.bias[st * 3 + 2] = bv[st]; qa.C[st * 3 + 2] = V[st];
        qa.A[st] = X[st];
    }
    qa.lens[0] = len0; qa.lens[1] = len1;

    const dim3 gEmbed(Mtot / 128, Dd / 128, 2);      // 256 x 4 x 2
    const dim3 gQKV  (Mtot / 128, Dd / 128, 6);      // 256 x 4 x 6
    const dim3 gScore(Ss / 128, Ss / 128, 32);       // 16 x 16 x 32

    tf32_embed<<<gEmbed, 256>>>(data0, know0, data1, know1, emb, Wt, bt, X[0], X[1]);
    tf32_qkv<<<gQKV, 256>>>(qa);
    tf32_scores<<<gScore, 256>>>(Q[0], K[0], Q[1], K[1], S[0], S[1], pMZp, len0, len1);
    combine_kernel<<<dim3(Ss / 256, Bb, 2), 256>>>(pMZp, pMZ, len0, len1);
    colsum_kernel<<<dim3(Ss / 256, Bb, 2), 256>>>(S[0], S[1], pMZ, pC, len0, len1);
    sumo_kernel<<<dim3(Dd / 128, Bb, 2), 128>>>(pC, V[0], V[1], pSO, len0, len1);
    sa_kernel<<<dim3(Dd / 256, Bb, 2), 256>>>(pSO, Wo[0], bo[0], Wo[1], bo[1], pCat);
    final_kernel<<<Bb, 256>>>(pCat, Wout, bout, out);
}